// round 2
// baseline (speedup 1.0000x reference)
#include <cuda_runtime.h>
#include <cuda_bf16.h>

#define NMAX 100000
#define CC   128
#define EMAX 1600000

// ---------------- scratch (static device globals; no allocation) -------------
__device__ float g_h   [(size_t)NMAX * CC];   // post-GEMM features
__device__ float g_h2  [(size_t)NMAX * CC];   // post-BN/ReLU features (layer-2 input)
__device__ float g_agg [(size_t)NMAX * CC];   // aggregated features
__device__ float g_dinv[NMAX];
__device__ int   g_deg [NMAX];
__device__ int   g_rowstart[NMAX + 1];
__device__ int   g_cursor[NMAX];
__device__ int   g_srcidx[EMAX];
__device__ float g_enorm [EMAX];
__device__ float g_sum[CC], g_sumsq[CC], g_scale[CC], g_shift[CC];

// ---------------- setup kernels ----------------------------------------------
__global__ void k_init_deg(int n) {
    int i = blockIdx.x * blockDim.x + threadIdx.x;
    if (i < n) g_deg[i] = 0;
    if (i < CC) { g_sum[i] = 0.f; g_sumsq[i] = 0.f; }
}

__global__ void k_count(const int* __restrict__ ei, int E) {
    int e = blockIdx.x * blockDim.x + threadIdx.x;
    if (e >= E) return;
    int d = ei[E + e];
    atomicAdd(&g_deg[d], 1);
}

__global__ void k_dinv(int n) {
    int i = blockIdx.x * blockDim.x + threadIdx.x;
    if (i < n) g_dinv[i] = rsqrtf((float)g_deg[i] + 1.0f);
}

// single-block exclusive scan of g_deg -> g_rowstart (and g_cursor)
__global__ void k_scan(int n) {
    __shared__ int s[1024];
    int t = threadIdx.x;
    int running = 0;
    for (int base = 0; base < n; base += 1024) {
        int i = base + t;
        int v = (i < n) ? g_deg[i] : 0;
        s[t] = v;
        __syncthreads();
        for (int off = 1; off < 1024; off <<= 1) {
            int add = (t >= off) ? s[t - off] : 0;
            __syncthreads();
            s[t] += add;
            __syncthreads();
        }
        if (i < n) {
            int excl = running + s[t] - v;
            g_rowstart[i] = excl;
            g_cursor[i]   = excl;
        }
        int tot = s[1023];
        __syncthreads();
        running += tot;
    }
    if (t == 0) g_rowstart[n] = running;
}

__global__ void k_fill(const int* __restrict__ ei, int E) {
    int e = blockIdx.x * blockDim.x + threadIdx.x;
    if (e >= E) return;
    int sN = ei[e];
    int d  = ei[E + e];
    int p = atomicAdd(&g_cursor[d], 1);
    g_srcidx[p] = sN;
    g_enorm[p]  = g_dinv[sN] * g_dinv[d];
}

// ---------------- GEMM: H = X @ W  (X:[n,128], W:[128,128]) ------------------
__global__ __launch_bounds__(256) void k_gemm(const float* __restrict__ X,
                                              const float* __restrict__ W,
                                              float* __restrict__ H, int n) {
    __shared__ float As[64 * 32];
    __shared__ float Bs[32 * 128];
    int tid = threadIdx.x;
    int tx = tid & 31;        // col group: cols tx*4 .. tx*4+3
    int ty = tid >> 5;        // row group: rows ty*8 .. ty*8+7
    int br = blockIdx.x * 64;

    float acc[8][4];
#pragma unroll
    for (int r = 0; r < 8; r++)
#pragma unroll
        for (int j = 0; j < 4; j++) acc[r][j] = 0.f;

    for (int kt = 0; kt < 128; kt += 32) {
        // load A tile: 64x32 = 512 float4
#pragma unroll
        for (int i = 0; i < 2; i++) {
            int f = tid + i * 256;
            int row = f >> 3, kc = f & 7;
            float4 v = make_float4(0.f, 0.f, 0.f, 0.f);
            int gr = br + row;
            if (gr < n) v = *(const float4*)(X + (size_t)gr * 128 + kt + kc * 4);
            *(float4*)(As + row * 32 + kc * 4) = v;
        }
        // load B tile: 32x128 = 1024 float4
#pragma unroll
        for (int i = 0; i < 4; i++) {
            int f = tid + i * 256;
            int kr = f >> 5, c4 = f & 31;
            *(float4*)(Bs + kr * 128 + c4 * 4) =
                *(const float4*)(W + (size_t)(kt + kr) * 128 + c4 * 4);
        }
        __syncthreads();
#pragma unroll
        for (int k = 0; k < 32; k++) {
            float4 b = *(const float4*)(Bs + k * 128 + tx * 4);
#pragma unroll
            for (int r = 0; r < 8; r++) {
                float a = As[(ty * 8 + r) * 32 + k];
                acc[r][0] += a * b.x;
                acc[r][1] += a * b.y;
                acc[r][2] += a * b.z;
                acc[r][3] += a * b.w;
            }
        }
        __syncthreads();
    }
#pragma unroll
    for (int r = 0; r < 8; r++) {
        int gr = br + ty * 8 + r;
        if (gr < n)
            *(float4*)(H + (size_t)gr * 128 + tx * 4) =
                make_float4(acc[r][0], acc[r][1], acc[r][2], acc[r][3]);
    }
}

// ---------------- per-node CSR gather aggregation ----------------------------
// agg[v] = h[v]*dinv[v]^2 + b + sum_{e in in(v)} h[src_e]*norm_e
__global__ __launch_bounds__(256) void k_agg(const float* __restrict__ H,
                                             const float* __restrict__ b,
                                             float* __restrict__ AGG, int n) {
    int warp = (blockIdx.x * blockDim.x + threadIdx.x) >> 5;
    int lane = threadIdx.x & 31;
    if (warp >= n) return;
    int v = warp;
    float dinv = g_dinv[v];
    float self = dinv * dinv;
    float4 hv = *(const float4*)(H + (size_t)v * 128 + lane * 4);
    float4 bv = *(const float4*)(b + lane * 4);
    float4 acc;
    acc.x = hv.x * self + bv.x;
    acc.y = hv.y * self + bv.y;
    acc.z = hv.z * self + bv.z;
    acc.w = hv.w * self + bv.w;

    int rs = g_rowstart[v], re = g_rowstart[v + 1];
    int e = rs;
    for (; e + 2 <= re; e += 2) {
        int s0 = g_srcidx[e], s1 = g_srcidx[e + 1];
        float n0 = g_enorm[e], n1 = g_enorm[e + 1];
        float4 h0 = *(const float4*)(H + (size_t)s0 * 128 + lane * 4);
        float4 h1 = *(const float4*)(H + (size_t)s1 * 128 + lane * 4);
        acc.x += h0.x * n0 + h1.x * n1;
        acc.y += h0.y * n0 + h1.y * n1;
        acc.z += h0.z * n0 + h1.z * n1;
        acc.w += h0.w * n0 + h1.w * n1;
    }
    if (e < re) {
        int s0 = g_srcidx[e];
        float n0 = g_enorm[e];
        float4 h0 = *(const float4*)(H + (size_t)s0 * 128 + lane * 4);
        acc.x += h0.x * n0;
        acc.y += h0.y * n0;
        acc.z += h0.z * n0;
        acc.w += h0.w * n0;
    }
    *(float4*)(AGG + (size_t)v * 128 + lane * 4) = acc;
}

// ---------------- batchnorm ---------------------------------------------------
__global__ void k_zero_stats() {
    int c = threadIdx.x;
    g_sum[c] = 0.f;
    g_sumsq[c] = 0.f;
}

__global__ __launch_bounds__(128) void k_stats(const float* __restrict__ A, int n) {
    int c = threadIdx.x;  // 128 threads = channels
    int nb = gridDim.x;
    int chunk = (n + nb - 1) / nb;
    int r0 = blockIdx.x * chunk;
    int r1 = min(n, r0 + chunk);
    float s = 0.f, sq = 0.f;
    for (int r = r0; r < r1; r++) {
        float v = A[(size_t)r * 128 + c];
        s += v;
        sq += v * v;
    }
    atomicAdd(&g_sum[c], s);
    atomicAdd(&g_sumsq[c], sq);
}

__global__ void k_bn_final(const float* __restrict__ gamma,
                           const float* __restrict__ beta, int n) {
    int c = threadIdx.x;
    float invn = 1.0f / (float)n;
    float m = g_sum[c] * invn;
    float var = g_sumsq[c] * invn - m * m;
    float rstd = rsqrtf(var + 1e-5f);
    float sc = gamma[c] * rstd;
    g_scale[c] = sc;
    g_shift[c] = beta[c] - m * sc;
}

// y = relu(a*scale + shift)
__global__ void k_apply_relu(const float* __restrict__ A, float* __restrict__ O,
                             int total4) {
    int i = blockIdx.x * blockDim.x + threadIdx.x;
    if (i >= total4) return;
    int c4 = i & 31;
    float4 sc = ((const float4*)g_scale)[c4];
    float4 sh = ((const float4*)g_shift)[c4];
    float4 a = ((const float4*)A)[i];
    float4 o;
    o.x = fmaxf(fmaf(a.x, sc.x, sh.x), 0.f);
    o.y = fmaxf(fmaf(a.y, sc.y, sh.y), 0.f);
    o.z = fmaxf(fmaf(a.z, sc.z, sh.z), 0.f);
    o.w = fmaxf(fmaf(a.w, sc.w, sh.w), 0.f);
    ((float4*)O)[i] = o;
}

// y = relu(a*scale + shift + x)   (residual)
__global__ void k_apply_relu_res(const float* __restrict__ A,
                                 const float* __restrict__ X,
                                 float* __restrict__ O, int total4) {
    int i = blockIdx.x * blockDim.x + threadIdx.x;
    if (i >= total4) return;
    int c4 = i & 31;
    float4 sc = ((const float4*)g_scale)[c4];
    float4 sh = ((const float4*)g_shift)[c4];
    float4 a = ((const float4*)A)[i];
    float4 x = ((const float4*)X)[i];
    float4 o;
    o.x = fmaxf(fmaf(a.x, sc.x, sh.x) + x.x, 0.f);
    o.y = fmaxf(fmaf(a.y, sc.y, sh.y) + x.y, 0.f);
    o.z = fmaxf(fmaf(a.z, sc.z, sh.z) + x.z, 0.f);
    o.w = fmaxf(fmaf(a.w, sc.w, sh.w) + x.w, 0.f);
    ((float4*)O)[i] = o;
}

// ---------------- launch ------------------------------------------------------
extern "C" void kernel_launch(void* const* d_in, const int* in_sizes, int n_in,
                              void* d_out, int out_size) {
    const float* x     = (const float*)d_in[0];
    const float* W1    = (const float*)d_in[1];
    const float* b1    = (const float*)d_in[2];
    const float* W2    = (const float*)d_in[3];
    const float* b2    = (const float*)d_in[4];
    const float* gamma = (const float*)d_in[5];
    const float* beta  = (const float*)d_in[6];
    const int*   ei    = (const int*)d_in[7];   // int32 [2, E] (JAX downgrades int64)

    int n = in_sizes[0] / CC;
    int E = in_sizes[7] / 2;
    float* out = (float*)d_out;

    float *p_h, *p_h2, *p_agg;
    cudaGetSymbolAddress((void**)&p_h,   g_h);
    cudaGetSymbolAddress((void**)&p_h2,  g_h2);
    cudaGetSymbolAddress((void**)&p_agg, g_agg);

    int nb_n = (n + 255) / 256;
    int nb_e = (E + 255) / 256;
    int total4 = n * (CC / 4);
    int nb_ew = (n * 32 + 255) / 256;  // warp-per-node
    int nb_4  = (total4 + 255) / 256;

    // --- CSR setup (shared by both layers) ---
    k_init_deg<<<nb_n, 256>>>(n);
    k_count<<<nb_e, 256>>>(ei, E);
    k_dinv<<<nb_n, 256>>>(n);
    k_scan<<<1, 1024>>>(n);
    k_fill<<<nb_e, 256>>>(ei, E);

    // --- layer 1 ---
    k_gemm<<<(n + 63) / 64, 256>>>(x, W1, p_h, n);
    k_agg<<<nb_ew, 256>>>(p_h, b1, p_agg, n);
    k_zero_stats<<<1, 128>>>();
    k_stats<<<256, 128>>>(p_agg, n);
    k_bn_final<<<1, 128>>>(gamma, beta, n);
    k_apply_relu<<<nb_4, 256>>>(p_agg, p_h2, total4);

    // --- layer 2 ---
    k_gemm<<<(n + 63) / 64, 256>>>(p_h2, W2, p_h, n);
    k_agg<<<nb_ew, 256>>>(p_h, b2, p_agg, n);
    k_zero_stats<<<1, 128>>>();
    k_stats<<<256, 128>>>(p_agg, n);
    k_bn_final<<<1, 128>>>(gamma, beta, n);
    k_apply_relu_res<<<nb_4, 256>>>(p_agg, x, out, total4);
}

// round 3
// speedup vs baseline: 1.3752x; 1.3752x over previous
#include <cuda_runtime.h>
#include <cuda_bf16.h>

#define NMAX 100000
#define CC   128
#define EMAX 1600000
#define SCAN_B 1024

// ---------------- scratch (static device globals; no allocation) -------------
__device__ float g_h   [(size_t)NMAX * CC];   // post-GEMM features
__device__ float g_agg [(size_t)NMAX * CC];   // aggregated features
__device__ float g_dinv[NMAX];
__device__ int   g_deg [NMAX];
__device__ int   g_rowstart[NMAX + 1];
__device__ int   g_cursor[NMAX];
__device__ int   g_srcidx[EMAX];
__device__ float g_enorm [EMAX];
__device__ int   g_part[256];
__device__ int   g_partbase[256];
__device__ float g_sum[CC], g_sumsq[CC], g_scale[CC], g_shift[CC];

// ---------------- setup kernels ----------------------------------------------
__global__ void k_init_deg(int n) {
    int i = blockIdx.x * blockDim.x + threadIdx.x;
    if (i < n) g_deg[i] = 0;
}

__global__ void k_count(const int* __restrict__ ei, int E) {
    int e = blockIdx.x * blockDim.x + threadIdx.x;
    if (e >= E) return;
    int d = ei[E + e];
    atomicAdd(&g_deg[d], 1);
}

__global__ void k_dinv(int n) {
    int i = blockIdx.x * blockDim.x + threadIdx.x;
    if (i < n) g_dinv[i] = rsqrtf((float)g_deg[i] + 1.0f);
}

// ---- 3-phase parallel exclusive scan of g_deg -> g_rowstart ------------------
// phase 1: per-block inclusive scan; write exclusive-in-block + block total
__global__ __launch_bounds__(SCAN_B) void k_scan1(int n) {
    __shared__ int s[SCAN_B];
    int t = threadIdx.x;
    int i = blockIdx.x * SCAN_B + t;
    int v = (i < n) ? g_deg[i] : 0;
    s[t] = v;
    __syncthreads();
#pragma unroll
    for (int off = 1; off < SCAN_B; off <<= 1) {
        int add = (t >= off) ? s[t - off] : 0;
        __syncthreads();
        s[t] += add;
        __syncthreads();
    }
    if (i < n) g_rowstart[i] = s[t] - v;   // exclusive within block
    if (t == SCAN_B - 1) g_part[blockIdx.x] = s[t];
}

// phase 2: single small block scans the block totals (nb <= 256)
__global__ void k_scan2(int nb, int n) {
    __shared__ int s[256];
    int t = threadIdx.x;
    int v = (t < nb) ? g_part[t] : 0;
    s[t] = v;
    __syncthreads();
#pragma unroll
    for (int off = 1; off < 256; off <<= 1) {
        int add = (t >= off) ? s[t - off] : 0;
        __syncthreads();
        s[t] += add;
        __syncthreads();
    }
    if (t < nb) g_partbase[t] = s[t] - v;  // exclusive base per block
    if (t == 255) g_rowstart[n] = s[255];  // total = E
}

// phase 3: add base, init cursor
__global__ __launch_bounds__(SCAN_B) void k_scan3(int n) {
    int i = blockIdx.x * SCAN_B + threadIdx.x;
    if (i >= n) return;
    int r = g_rowstart[i] + g_partbase[blockIdx.x];
    g_rowstart[i] = r;
    g_cursor[i]   = r;
}

__global__ void k_fill(const int* __restrict__ ei, int E) {
    int e = blockIdx.x * blockDim.x + threadIdx.x;
    if (e >= E) return;
    int sN = ei[e];
    int d  = ei[E + e];
    int p = atomicAdd(&g_cursor[d], 1);
    g_srcidx[p] = sN;
    g_enorm[p]  = g_dinv[sN] * g_dinv[d];
}

// ---------------- GEMM: H = X @ W  (X:[n,128], W:[128,128]) ------------------
// BN_FUSE: if true, A elements are transformed relu(a*scale[ch]+shift[ch]) on load
template <bool BN_FUSE>
__global__ __launch_bounds__(256) void k_gemm(const float* __restrict__ X,
                                              const float* __restrict__ W,
                                              float* __restrict__ H, int n) {
    __shared__ float As[64 * 32];
    __shared__ float Bs[32 * 128];
    int tid = threadIdx.x;
    int tx = tid & 31;        // col group: cols tx*4 .. tx*4+3
    int ty = tid >> 5;        // row group: rows ty*8 .. ty*8+7
    int br = blockIdx.x * 64;

    float acc[8][4];
#pragma unroll
    for (int r = 0; r < 8; r++)
#pragma unroll
        for (int j = 0; j < 4; j++) acc[r][j] = 0.f;

    for (int kt = 0; kt < 128; kt += 32) {
        // load A tile: 64x32 = 512 float4
#pragma unroll
        for (int i = 0; i < 2; i++) {
            int f = tid + i * 256;
            int row = f >> 3, kc = f & 7;
            float4 v = make_float4(0.f, 0.f, 0.f, 0.f);
            int gr = br + row;
            if (gr < n) {
                v = *(const float4*)(X + (size_t)gr * 128 + kt + kc * 4);
                if (BN_FUSE) {
                    int f4 = (kt >> 2) + kc;
                    float4 sc = ((const float4*)g_scale)[f4];
                    float4 sh = ((const float4*)g_shift)[f4];
                    v.x = fmaxf(fmaf(v.x, sc.x, sh.x), 0.f);
                    v.y = fmaxf(fmaf(v.y, sc.y, sh.y), 0.f);
                    v.z = fmaxf(fmaf(v.z, sc.z, sh.z), 0.f);
                    v.w = fmaxf(fmaf(v.w, sc.w, sh.w), 0.f);
                }
            }
            *(float4*)(As + row * 32 + kc * 4) = v;
        }
        // load B tile: 32x128 = 1024 float4
#pragma unroll
        for (int i = 0; i < 4; i++) {
            int f = tid + i * 256;
            int kr = f >> 5, c4 = f & 31;
            *(float4*)(Bs + kr * 128 + c4 * 4) =
                *(const float4*)(W + (size_t)(kt + kr) * 128 + c4 * 4);
        }
        __syncthreads();
#pragma unroll
        for (int k = 0; k < 32; k++) {
            float4 b = *(const float4*)(Bs + k * 128 + tx * 4);
#pragma unroll
            for (int r = 0; r < 8; r++) {
                float a = As[(ty * 8 + r) * 32 + k];
                acc[r][0] += a * b.x;
                acc[r][1] += a * b.y;
                acc[r][2] += a * b.z;
                acc[r][3] += a * b.w;
            }
        }
        __syncthreads();
    }
#pragma unroll
    for (int r = 0; r < 8; r++) {
        int gr = br + ty * 8 + r;
        if (gr < n)
            *(float4*)(H + (size_t)gr * 128 + tx * 4) =
                make_float4(acc[r][0], acc[r][1], acc[r][2], acc[r][3]);
    }
}

// ---------------- per-node CSR gather aggregation ----------------------------
// agg[v] = h[v]*dinv[v]^2 + b + sum_{e in in(v)} h[src_e]*norm_e
__global__ __launch_bounds__(256) void k_agg(const float* __restrict__ H,
                                             const float* __restrict__ b,
                                             float* __restrict__ AGG, int n) {
    int warp = (blockIdx.x * blockDim.x + threadIdx.x) >> 5;
    int lane = threadIdx.x & 31;
    if (warp >= n) return;
    int v = warp;
    float dinv = g_dinv[v];
    float self = dinv * dinv;
    float4 hv = *(const float4*)(H + (size_t)v * 128 + lane * 4);
    float4 bv = *(const float4*)(b + lane * 4);
    float4 acc;
    acc.x = hv.x * self + bv.x;
    acc.y = hv.y * self + bv.y;
    acc.z = hv.z * self + bv.z;
    acc.w = hv.w * self + bv.w;

    int rs = g_rowstart[v], re = g_rowstart[v + 1];
    int e = rs;
    for (; e + 2 <= re; e += 2) {
        int s0 = g_srcidx[e], s1 = g_srcidx[e + 1];
        float n0 = g_enorm[e], n1 = g_enorm[e + 1];
        float4 h0 = *(const float4*)(H + (size_t)s0 * 128 + lane * 4);
        float4 h1 = *(const float4*)(H + (size_t)s1 * 128 + lane * 4);
        acc.x += h0.x * n0 + h1.x * n1;
        acc.y += h0.y * n0 + h1.y * n1;
        acc.z += h0.z * n0 + h1.z * n1;
        acc.w += h0.w * n0 + h1.w * n1;
    }
    if (e < re) {
        int s0 = g_srcidx[e];
        float n0 = g_enorm[e];
        float4 h0 = *(const float4*)(H + (size_t)s0 * 128 + lane * 4);
        acc.x += h0.x * n0;
        acc.y += h0.y * n0;
        acc.z += h0.z * n0;
        acc.w += h0.w * n0;
    }
    *(float4*)(AGG + (size_t)v * 128 + lane * 4) = acc;
}

// ---------------- batchnorm ---------------------------------------------------
__global__ void k_zero_stats() {
    int c = threadIdx.x;
    g_sum[c] = 0.f;
    g_sumsq[c] = 0.f;
}

__global__ __launch_bounds__(128) void k_stats(const float* __restrict__ A, int n) {
    int c = threadIdx.x;  // 128 threads = channels
    int nb = gridDim.x;
    int chunk = (n + nb - 1) / nb;
    int r0 = blockIdx.x * chunk;
    int r1 = min(n, r0 + chunk);
    float s = 0.f, sq = 0.f;
    for (int r = r0; r < r1; r++) {
        float v = A[(size_t)r * 128 + c];
        s += v;
        sq += v * v;
    }
    atomicAdd(&g_sum[c], s);
    atomicAdd(&g_sumsq[c], sq);
}

__global__ void k_bn_final(const float* __restrict__ gamma,
                           const float* __restrict__ beta, int n) {
    int c = threadIdx.x;
    float invn = 1.0f / (float)n;
    float m = g_sum[c] * invn;
    float var = g_sumsq[c] * invn - m * m;
    float rstd = rsqrtf(var + 1e-5f);
    float sc = gamma[c] * rstd;
    g_scale[c] = sc;
    g_shift[c] = beta[c] - m * sc;
}

// y = relu(a*scale + shift + x)   (residual; final output)
__global__ void k_apply_relu_res(const float* __restrict__ A,
                                 const float* __restrict__ X,
                                 float* __restrict__ O, int total4) {
    int i = blockIdx.x * blockDim.x + threadIdx.x;
    if (i >= total4) return;
    int c4 = i & 31;
    float4 sc = ((const float4*)g_scale)[c4];
    float4 sh = ((const float4*)g_shift)[c4];
    float4 a = ((const float4*)A)[i];
    float4 x = ((const float4*)X)[i];
    float4 o;
    o.x = fmaxf(fmaf(a.x, sc.x, sh.x) + x.x, 0.f);
    o.y = fmaxf(fmaf(a.y, sc.y, sh.y) + x.y, 0.f);
    o.z = fmaxf(fmaf(a.z, sc.z, sh.z) + x.z, 0.f);
    o.w = fmaxf(fmaf(a.w, sc.w, sh.w) + x.w, 0.f);
    ((float4*)O)[i] = o;
}

// ---------------- launch ------------------------------------------------------
extern "C" void kernel_launch(void* const* d_in, const int* in_sizes, int n_in,
                              void* d_out, int out_size) {
    const float* x     = (const float*)d_in[0];
    const float* W1    = (const float*)d_in[1];
    const float* b1    = (const float*)d_in[2];
    const float* W2    = (const float*)d_in[3];
    const float* b2    = (const float*)d_in[4];
    const float* gamma = (const float*)d_in[5];
    const float* beta  = (const float*)d_in[6];
    const int*   ei    = (const int*)d_in[7];   // int32 [2, E]

    int n = in_sizes[0] / CC;
    int E = in_sizes[7] / 2;
    float* out = (float*)d_out;

    float *p_h, *p_agg;
    cudaGetSymbolAddress((void**)&p_h,   g_h);
    cudaGetSymbolAddress((void**)&p_agg, g_agg);

    int nb_n  = (n + 255) / 256;
    int nb_e  = (E + 255) / 256;
    int nb_sc = (n + SCAN_B - 1) / SCAN_B;     // <= 98 blocks (fits 256 partials)
    int total4 = n * (CC / 4);
    int nb_ew = (n * 32 + 255) / 256;          // warp-per-node
    int nb_4  = (total4 + 255) / 256;

    // --- CSR setup (shared by both layers) ---
    k_init_deg<<<nb_n, 256>>>(n);
    k_count<<<nb_e, 256>>>(ei, E);
    k_dinv<<<nb_n, 256>>>(n);
    k_scan1<<<nb_sc, SCAN_B>>>(n);
    k_scan2<<<1, 256>>>(nb_sc, n);
    k_scan3<<<nb_sc, SCAN_B>>>(n);
    k_fill<<<nb_e, 256>>>(ei, E);

    // --- layer 1 ---
    k_gemm<false><<<(n + 63) / 64, 256>>>(x, W1, p_h, n);
    k_agg<<<nb_ew, 256>>>(p_h, b1, p_agg, n);
    k_zero_stats<<<1, 128>>>();
    k_stats<<<512, 128>>>(p_agg, n);
    k_bn_final<<<1, 128>>>(gamma, beta, n);

    // --- layer 2 (BN+ReLU of layer 1 fused into A-tile load) ---
    k_gemm<true><<<(n + 63) / 64, 256>>>(p_agg, W2, p_h, n);
    k_agg<<<nb_ew, 256>>>(p_h, b2, p_agg, n);
    k_zero_stats<<<1, 128>>>();
    k_stats<<<512, 128>>>(p_agg, n);
    k_bn_final<<<1, 128>>>(gamma, beta, n);
    k_apply_relu_res<<<nb_4, 256>>>(p_agg, x, out, total4);
}